// round 1
// baseline (speedup 1.0000x reference)
#include <cuda_runtime.h>
#include <cuda_bf16.h>
#include <math.h>

// Problem shapes (fixed)
#define Bsz 8
#define Sq  2048
#define Dd  512
#define Hh  512
#define MS  (Bsz * Sq)           // 16384 rows for x / q / k / v / ctx

// GEMM tiling
#define BM 128
#define BN 128
#define BK 8
#define TM 8
#define TN 8
#define NTHREADS 256

// -------- scratch (device globals; no allocation allowed) --------
__device__ float g_q[(long)MS * Hh];       // 33.5 MB
__device__ float g_k[(long)MS * Hh];
__device__ float g_v[(long)MS * Hh];
__device__ float g_ctx[(long)MS * Hh];
__device__ float g_scores[(long)Bsz * Sq * Sq];  // 134 MB

// ---------------------------------------------------------------------------
// NN GEMM: C[M,N] = alpha * A[M,K] @ B[K,N] (+ bias[N]) (+ res)
// A row-major lda=K, B row-major ldb=N, C row-major ldc=N.
// Per-z strides for batched use. Assumes M%BM==0, N%BN==0, K%BK==0,
// N%4==0, K%4==0 (true for all uses here).
// ---------------------------------------------------------------------------
__global__ __launch_bounds__(NTHREADS) void gemm_nn(
    const float* __restrict__ A, const float* __restrict__ B,
    const float* __restrict__ bias, const float* __restrict__ res,
    float* __restrict__ C,
    int M, int N, int K, float alpha,
    long sA, long sB, long sC)
{
    A += (long)blockIdx.z * sA;
    B += (long)blockIdx.z * sB;
    C += (long)blockIdx.z * sC;
    if (res) res += (long)blockIdx.z * sC;

    __shared__ float As[BK][BM];
    __shared__ float Bs[BK][BN];

    const int t  = threadIdx.x;
    const int m0 = blockIdx.x * BM;
    const int n0 = blockIdx.y * BN;

    const int arow = t >> 1,  acol = (t & 1) * 4;   // A loader: 128 rows x 8 k
    const int brow = t >> 5,  bcol = (t & 31) * 4;  // B loader: 8 k x 128 n
    const int tx = t & 15, ty = t >> 4;             // 16x16 compute layout

    float acc[TM][TN];
#pragma unroll
    for (int i = 0; i < TM; i++)
#pragma unroll
        for (int j = 0; j < TN; j++) acc[i][j] = 0.f;

    for (int k0 = 0; k0 < K; k0 += BK) {
        float4 av = *(const float4*)(A + (long)(m0 + arow) * K + k0 + acol);
        As[acol + 0][arow] = av.x;
        As[acol + 1][arow] = av.y;
        As[acol + 2][arow] = av.z;
        As[acol + 3][arow] = av.w;
        float4 bv = *(const float4*)(B + (long)(k0 + brow) * N + n0 + bcol);
        *(float4*)&Bs[brow][bcol] = bv;
        __syncthreads();

#pragma unroll
        for (int k = 0; k < BK; k++) {
            float a[TM], b[TN];
            *(float4*)(a)     = *(const float4*)&As[k][ty * TM];
            *(float4*)(a + 4) = *(const float4*)&As[k][ty * TM + 4];
            *(float4*)(b)     = *(const float4*)&Bs[k][tx * TN];
            *(float4*)(b + 4) = *(const float4*)&Bs[k][tx * TN + 4];
#pragma unroll
            for (int i = 0; i < TM; i++)
#pragma unroll
                for (int j = 0; j < TN; j++)
                    acc[i][j] = fmaf(a[i], b[j], acc[i][j]);
        }
        __syncthreads();
    }

#pragma unroll
    for (int i = 0; i < TM; i++) {
        const long row = m0 + ty * TM + i;
#pragma unroll
        for (int j = 0; j < TN; j += 4) {
            const int col = n0 + tx * TN + j;
            float4 v;
            v.x = acc[i][j + 0] * alpha;
            v.y = acc[i][j + 1] * alpha;
            v.z = acc[i][j + 2] * alpha;
            v.w = acc[i][j + 3] * alpha;
            if (bias) {
                const float4 bb = *(const float4*)(bias + col);
                v.x += bb.x; v.y += bb.y; v.z += bb.z; v.w += bb.w;
            }
            if (res) {
                const float4 r = *(const float4*)(res + row * N + col);
                v.x += r.x; v.y += r.y; v.z += r.z; v.w += r.w;
            }
            *(float4*)(C + row * N + col) = v;
        }
    }
}

// ---------------------------------------------------------------------------
// NT GEMM: C[M,N] = alpha * A[M,K] @ B[N,K]^T
// Both A and B row-major with leading dim K. Used for scores = Q @ K^T.
// ---------------------------------------------------------------------------
__global__ __launch_bounds__(NTHREADS) void gemm_nt(
    const float* __restrict__ A, const float* __restrict__ B,
    float* __restrict__ C,
    int M, int N, int K, float alpha,
    long sA, long sB, long sC)
{
    A += (long)blockIdx.z * sA;
    B += (long)blockIdx.z * sB;
    C += (long)blockIdx.z * sC;

    __shared__ float As[BK][BM];
    __shared__ float Bs[BK][BN];

    const int t  = threadIdx.x;
    const int m0 = blockIdx.x * BM;
    const int n0 = blockIdx.y * BN;

    const int arow = t >> 1, acol = (t & 1) * 4;
    const int tx = t & 15, ty = t >> 4;

    float acc[TM][TN];
#pragma unroll
    for (int i = 0; i < TM; i++)
#pragma unroll
        for (int j = 0; j < TN; j++) acc[i][j] = 0.f;

    for (int k0 = 0; k0 < K; k0 += BK) {
        float4 av = *(const float4*)(A + (long)(m0 + arow) * K + k0 + acol);
        As[acol + 0][arow] = av.x;
        As[acol + 1][arow] = av.y;
        As[acol + 2][arow] = av.z;
        As[acol + 3][arow] = av.w;
        // B is [N, K]; transpose-load into Bs[k][n]
        float4 bv = *(const float4*)(B + (long)(n0 + arow) * K + k0 + acol);
        Bs[acol + 0][arow] = bv.x;
        Bs[acol + 1][arow] = bv.y;
        Bs[acol + 2][arow] = bv.z;
        Bs[acol + 3][arow] = bv.w;
        __syncthreads();

#pragma unroll
        for (int k = 0; k < BK; k++) {
            float a[TM], b[TN];
            *(float4*)(a)     = *(const float4*)&As[k][ty * TM];
            *(float4*)(a + 4) = *(const float4*)&As[k][ty * TM + 4];
            *(float4*)(b)     = *(const float4*)&Bs[k][tx * TN];
            *(float4*)(b + 4) = *(const float4*)&Bs[k][tx * TN + 4];
#pragma unroll
            for (int i = 0; i < TM; i++)
#pragma unroll
                for (int j = 0; j < TN; j++)
                    acc[i][j] = fmaf(a[i], b[j], acc[i][j]);
        }
        __syncthreads();
    }

#pragma unroll
    for (int i = 0; i < TM; i++) {
        const long row = m0 + ty * TM + i;
#pragma unroll
        for (int j = 0; j < TN; j += 4) {
            const int col = n0 + tx * TN + j;
            float4 v;
            v.x = acc[i][j + 0] * alpha;
            v.y = acc[i][j + 1] * alpha;
            v.z = acc[i][j + 2] * alpha;
            v.w = acc[i][j + 3] * alpha;
            *(float4*)(C + row * N + col) = v;
        }
    }
}

// ---------------------------------------------------------------------------
// Row-wise softmax in place over [rows, cols], one block per row.
// ---------------------------------------------------------------------------
__global__ __launch_bounds__(256) void softmax_rows(float* __restrict__ S, int cols)
{
    const long row = blockIdx.x;
    float* p = S + row * (long)cols;
    __shared__ float red[256];
    const int t = threadIdx.x;

    float m = -1e30f;
    for (int c = t; c < cols; c += 256) m = fmaxf(m, p[c]);
    red[t] = m;
    __syncthreads();
    for (int s = 128; s > 0; s >>= 1) {
        if (t < s) red[t] = fmaxf(red[t], red[t + s]);
        __syncthreads();
    }
    m = red[0];
    __syncthreads();

    float sum = 0.f;
    for (int c = t; c < cols; c += 256) {
        float e = __expf(p[c] - m);
        p[c] = e;
        sum += e;
    }
    red[t] = sum;
    __syncthreads();
    for (int s = 128; s > 0; s >>= 1) {
        if (t < s) red[t] += red[t + s];
        __syncthreads();
    }
    const float inv = 1.f / red[0];
    __syncthreads();

    for (int c = t; c < cols; c += 256) p[c] *= inv;
}

// ---------------------------------------------------------------------------
// launch
// ---------------------------------------------------------------------------
extern "C" void kernel_launch(void* const* d_in, const int* in_sizes, int n_in,
                              void* d_out, int out_size)
{
    const float* x  = (const float*)d_in[0];
    const float* Wq = (const float*)d_in[1];
    const float* bq = (const float*)d_in[2];
    const float* Wk = (const float*)d_in[3];
    const float* bk = (const float*)d_in[4];
    const float* Wv = (const float*)d_in[5];
    const float* bv = (const float*)d_in[6];
    const float* Wo = (const float*)d_in[7];
    const float* bo = (const float*)d_in[8];
    float* out = (float*)d_out;

    float *q, *k, *v, *ctx, *sc;
    cudaGetSymbolAddress((void**)&q,   g_q);
    cudaGetSymbolAddress((void**)&k,   g_k);
    cudaGetSymbolAddress((void**)&v,   g_v);
    cudaGetSymbolAddress((void**)&ctx, g_ctx);
    cudaGetSymbolAddress((void**)&sc,  g_scores);

    dim3 thr(NTHREADS);

    // 1) QKV projections: [16384,512] @ [512,512] (+bias, zero here but generic)
    {
        dim3 grid(MS / BM, Hh / BN, 1);
        gemm_nn<<<grid, thr>>>(x, Wq, bq, nullptr, q, MS, Hh, Dd, 1.f, 0, 0, 0);
        gemm_nn<<<grid, thr>>>(x, Wk, bk, nullptr, k, MS, Hh, Dd, 1.f, 0, 0, 0);
        gemm_nn<<<grid, thr>>>(x, Wv, bv, nullptr, v, MS, Hh, Dd, 1.f, 0, 0, 0);
    }

    // 2) scores = Q @ K^T / sqrt(H), per batch
    {
        dim3 grid(Sq / BM, Sq / BN, Bsz);
        const float alpha = 1.f / sqrtf((float)Hh);
        gemm_nt<<<grid, thr>>>(q, k, sc, Sq, Sq, Hh, alpha,
                               (long)Sq * Hh, (long)Sq * Hh, (long)Sq * Sq);
    }

    // 3) softmax over last dim
    softmax_rows<<<Bsz * Sq, 256>>>(sc, Sq);

    // 4) context = P @ V, per batch
    {
        dim3 grid(Sq / BM, Hh / BN, Bsz);
        gemm_nn<<<grid, thr>>>(sc, v, nullptr, nullptr, ctx, Sq, Hh, Sq, 1.f,
                               (long)Sq * Sq, (long)Sq * Hh, (long)Sq * Hh);
    }

    // 5) out = ctx @ Wo + bo + x
    {
        dim3 grid(MS / BM, Dd / BN, 1);
        gemm_nn<<<grid, thr>>>(ctx, Wo, bo, x, out, MS, Dd, Hh, 1.f, 0, 0, 0);
    }
}

// round 3
// speedup vs baseline: 3.5770x; 3.5770x over previous
#include <cuda_runtime.h>
#include <cstdint>
#include <math.h>

// Shapes (fixed)
#define Bsz 8
#define Sq  2048
#define Dd  512
#define Hh  512
#define MS  (Bsz * Sq)   // 16384

// ---------------- scratch (device globals) ----------------
__device__ float g_q  [(long)MS * Hh];
__device__ float g_k  [(long)MS * Hh];
__device__ float g_vT [(long)MS * Hh];      // [Hh, MS]
__device__ float g_ctx[(long)MS * Hh];
__device__ float g_sc [(long)Bsz * Sq * Sq];
__device__ float g_wqt[Dd * Hh];
__device__ float g_wkt[Dd * Hh];
__device__ float g_wvt[Dd * Hh];
__device__ float g_wot[Dd * Hh];

// ---------------- helpers ----------------
__device__ __forceinline__ uint32_t smem_u32(const void* p) {
    uint32_t a;
    asm("{ .reg .u64 t; cvta.to.shared.u64 t, %1; cvt.u32.u64 %0, t; }" : "=r"(a) : "l"(p));
    return a;
}
__device__ __forceinline__ uint32_t cvt_tf32(uint32_t x) {
    uint32_t r;
    asm("cvt.rna.tf32.f32 %0, %1;" : "=r"(r) : "f"(__uint_as_float(x)));
    return r;
}
#define LDSM4(r, a)                                                              \
    asm volatile("ldmatrix.sync.aligned.m8n8.x4.shared.b16 {%0,%1,%2,%3}, [%4];" \
                 : "=r"((r)[0]), "=r"((r)[1]), "=r"((r)[2]), "=r"((r)[3])        \
                 : "r"(a))
__device__ __forceinline__ void mma_tf32(float* c, const uint32_t* a,
                                         uint32_t b0, uint32_t b1) {
    asm volatile(
        "mma.sync.aligned.m16n8k8.row.col.f32.tf32.tf32.f32 "
        "{%0,%1,%2,%3}, {%4,%5,%6,%7}, {%8,%9}, {%0,%1,%2,%3};"
        : "+f"(c[0]), "+f"(c[1]), "+f"(c[2]), "+f"(c[3])
        : "r"(a[0]), "r"(a[1]), "r"(a[2]), "r"(a[3]), "r"(b0), "r"(b1));
}
#define CP_ASYNC(dst, src) \
    asm volatile("cp.async.cg.shared.global [%0], [%1], 16;" :: "r"(dst), "l"(src))
#define CP_COMMIT() asm volatile("cp.async.commit_group;" ::: "memory")
#define CP_WAIT(n)  asm volatile("cp.async.wait_group %0;" :: "n"(n) : "memory")

// ---------------- tf32 mma.sync NT GEMM ----------------
// C[M,N] = alpha * A[M,K] @ B[N,K]^T (+biasN[col]) (+biasM[row]) (+res)
// BM=BN=128, BK=32, 128 threads, 4 warps of 64x64.
#define RS 144                     // padded row stride bytes (36 floats)
#define B_OFF  (128 * RS)          // B tile after A tile within a stage
#define STAGE  (256 * RS)          // 36864 B
#define GSMEM_TOTAL (2 * STAGE)    // 73728 B

__device__ __forceinline__ void stage_load(
    uint32_t sbase, const float* __restrict__ A, long lda,
    const float* __restrict__ B, long ldb, int m0, int n0, int kt, int t)
{
    const int lrow = t >> 3, lch = t & 7;
#pragma unroll
    for (int i = 0; i < 8; i++) {
        const int row = lrow + i * 16;
        CP_ASYNC(sbase + row * RS + lch * 16,
                 A + (long)(m0 + row) * lda + kt + lch * 4);
    }
#pragma unroll
    for (int i = 0; i < 8; i++) {
        const int row = lrow + i * 16;
        CP_ASYNC(sbase + B_OFF + row * RS + lch * 16,
                 B + (long)(n0 + row) * ldb + kt + lch * 4);
    }
}

__global__ __launch_bounds__(128) void gemm_tf32_nt(
    const float* __restrict__ A, long lda, long sA,
    const float* __restrict__ B, long ldb, long sB,
    float* __restrict__ C, long ldc, long sC,
    const float* __restrict__ biasN, const float* __restrict__ biasM,
    const float* __restrict__ res, float alpha, int K)
{
    extern __shared__ __align__(128) char smem[];
    const uint32_t sb = smem_u32(smem);
    const int t = threadIdx.x;
    const int m0 = blockIdx.x * 128;
    const int n0 = blockIdx.y * 128;

    A += (long)blockIdx.z * sA;
    B += (long)blockIdx.z * sB;
    C += (long)blockIdx.z * sC;
    const float* resz = res ? res + (long)blockIdx.z * sC : nullptr;

    const int lane = t & 31, w = t >> 5;
    const int wm = w & 1, wn = w >> 1;

    // ldmatrix per-lane addressing
    const int arow = (lane & 7) + ((lane >> 3) & 1) * 8;   // 0..15 within m-tile
    const int akb  = (lane >> 4) * 16;                      // k byte offset {0,16}
    const int brow = ((lane >> 4) * 8) + (lane & 7);        // 0..15 within n-pair
    const int bkb  = ((lane >> 3) & 1) * 16;
    const uint32_t aB = sb + (wm * 64 + arow) * RS + akb;
    const uint32_t bB = sb + B_OFF + (wn * 64 + brow) * RS + bkb;

    float acc[4][8][4];
#pragma unroll
    for (int i = 0; i < 4; i++)
#pragma unroll
        for (int j = 0; j < 8; j++)
#pragma unroll
            for (int r = 0; r < 4; r++) acc[i][j][r] = 0.f;

    const int ktiles = K / 32;
    stage_load(sb, A, lda, B, ldb, m0, n0, 0, t);
    CP_COMMIT();

    for (int kt = 0; kt < ktiles; kt++) {
        if (kt + 1 < ktiles) {
            stage_load(sb + ((kt + 1) & 1) * STAGE, A, lda, B, ldb,
                       m0, n0, (kt + 1) * 32, t);
            CP_COMMIT();
            CP_WAIT(1);
        } else {
            CP_WAIT(0);
        }
        __syncthreads();

        const uint32_t so = (kt & 1) * STAGE;
#pragma unroll
        for (int s = 0; s < 4; s++) {
            uint32_t af[4][4], bf[4][4];
#pragma unroll
            for (int mt = 0; mt < 4; mt++)
                LDSM4(af[mt], aB + so + mt * (16 * RS) + s * 32);
#pragma unroll
            for (int p = 0; p < 4; p++)
                LDSM4(bf[p], bB + so + p * (16 * RS) + s * 32);
#pragma unroll
            for (int mt = 0; mt < 4; mt++)
#pragma unroll
                for (int r = 0; r < 4; r++) af[mt][r] = cvt_tf32(af[mt][r]);
#pragma unroll
            for (int p = 0; p < 4; p++)
#pragma unroll
                for (int r = 0; r < 4; r++) bf[p][r] = cvt_tf32(bf[p][r]);
#pragma unroll
            for (int mt = 0; mt < 4; mt++)
#pragma unroll
                for (int p = 0; p < 4; p++) {
                    mma_tf32(acc[mt][2 * p + 0], af[mt], bf[p][0], bf[p][1]);
                    mma_tf32(acc[mt][2 * p + 1], af[mt], bf[p][2], bf[p][3]);
                }
        }
        __syncthreads();
    }

    // epilogue
    const int gcol0 = (lane & 3) * 2;
    const int grow  = lane >> 2;
#pragma unroll
    for (int mt = 0; mt < 4; mt++) {
        const long row = m0 + wm * 64 + mt * 16 + grow;
        const float bm0 = biasM ? biasM[row] : 0.f;
        const float bm1 = biasM ? biasM[row + 8] : 0.f;
#pragma unroll
        for (int nt = 0; nt < 8; nt++) {
            const int col = n0 + wn * 64 + nt * 8 + gcol0;
            float2 v0, v1;
            v0.x = acc[mt][nt][0] * alpha + bm0;
            v0.y = acc[mt][nt][1] * alpha + bm0;
            v1.x = acc[mt][nt][2] * alpha + bm1;
            v1.y = acc[mt][nt][3] * alpha + bm1;
            if (biasN) {
                const float2 bb = *(const float2*)(biasN + col);
                v0.x += bb.x; v0.y += bb.y; v1.x += bb.x; v1.y += bb.y;
            }
            if (resz) {
                const float2 r0 = *(const float2*)(resz + row * ldc + col);
                const float2 r1 = *(const float2*)(resz + (row + 8) * ldc + col);
                v0.x += r0.x; v0.y += r0.y; v1.x += r1.x; v1.y += r1.y;
            }
            *(float2*)(C + row * ldc + col) = v0;
            *(float2*)(C + (row + 8) * ldc + col) = v1;
        }
    }
}

// ---------------- 512x512 transpose ----------------
__global__ __launch_bounds__(256) void transpose512(const float* __restrict__ W,
                                                    float* __restrict__ Wt)
{
    __shared__ float tile[32][33];
    const int tx = threadIdx.x, ty = threadIdx.y;  // 32 x 8
    int x = blockIdx.x * 32 + tx;
    int y = blockIdx.y * 32 + ty;
#pragma unroll
    for (int i = 0; i < 4; i++)
        tile[ty + i * 8][tx] = W[(y + i * 8) * 512 + x];
    __syncthreads();
    x = blockIdx.y * 32 + tx;
    y = blockIdx.x * 32 + ty;
#pragma unroll
    for (int i = 0; i < 4; i++)
        Wt[(y + i * 8) * 512 + x] = tile[tx][ty + i * 8];
}

// ---------------- softmax ----------------
__global__ __launch_bounds__(256) void softmax_rows(float* __restrict__ S, int cols)
{
    const long row = blockIdx.x;
    float* p = S + row * (long)cols;
    __shared__ float red[256];
    const int t = threadIdx.x;

    float m = -1e30f;
    for (int c = t; c < cols; c += 256) m = fmaxf(m, p[c]);
    red[t] = m;
    __syncthreads();
    for (int s = 128; s > 0; s >>= 1) {
        if (t < s) red[t] = fmaxf(red[t], red[t + s]);
        __syncthreads();
    }
    m = red[0];
    __syncthreads();

    float sum = 0.f;
    for (int c = t; c < cols; c += 256) {
        float e = __expf(p[c] - m);
        p[c] = e;
        sum += e;
    }
    red[t] = sum;
    __syncthreads();
    for (int s = 128; s > 0; s >>= 1) {
        if (t < s) red[t] += red[t + s];
        __syncthreads();
    }
    const float inv = 1.f / red[0];
    __syncthreads();
    for (int c = t; c < cols; c += 256) p[c] *= inv;
}

// ---------------- launch ----------------
extern "C" void kernel_launch(void* const* d_in, const int* in_sizes, int n_in,
                              void* d_out, int out_size)
{
    const float* x  = (const float*)d_in[0];
    const float* Wq = (const float*)d_in[1];
    const float* bq = (const float*)d_in[2];
    const float* Wk = (const float*)d_in[3];
    const float* bk = (const float*)d_in[4];
    const float* Wv = (const float*)d_in[5];
    const float* bv = (const float*)d_in[6];
    const float* Wo = (const float*)d_in[7];
    const float* bo = (const float*)d_in[8];
    float* out = (float*)d_out;

    float *q, *k, *vT, *ctx, *sc, *wqt, *wkt, *wvt, *wot;
    cudaGetSymbolAddress((void**)&q,   g_q);
    cudaGetSymbolAddress((void**)&k,   g_k);
    cudaGetSymbolAddress((void**)&vT,  g_vT);
    cudaGetSymbolAddress((void**)&ctx, g_ctx);
    cudaGetSymbolAddress((void**)&sc,  g_sc);
    cudaGetSymbolAddress((void**)&wqt, g_wqt);
    cudaGetSymbolAddress((void**)&wkt, g_wkt);
    cudaGetSymbolAddress((void**)&wvt, g_wvt);
    cudaGetSymbolAddress((void**)&wot, g_wot);

    static int smem_set = 0;
    if (!smem_set) {
        cudaFuncSetAttribute(gemm_tf32_nt,
                             cudaFuncAttributeMaxDynamicSharedMemorySize, GSMEM_TOTAL);
        smem_set = 1;
    }

    // 0) transpose weights: Wt[n,k] = W[k,n]
    {
        dim3 g(16, 16), b(32, 8);
        transpose512<<<g, b>>>(Wq, wqt);
        transpose512<<<g, b>>>(Wk, wkt);
        transpose512<<<g, b>>>(Wv, wvt);
        transpose512<<<g, b>>>(Wo, wot);
    }

    const float inv_sqrt_h = 1.f / sqrtf((float)Hh);

    // 1) q = x @ Wq (+bq)
    gemm_tf32_nt<<<dim3(MS / 128, Hh / 128, 1), 128, GSMEM_TOTAL>>>(
        x, Dd, 0, wqt, Dd, 0, q, Hh, 0, bq, nullptr, nullptr, 1.f, Dd);
    // 2) k = x @ Wk (+bk)
    gemm_tf32_nt<<<dim3(MS / 128, Hh / 128, 1), 128, GSMEM_TOTAL>>>(
        x, Dd, 0, wkt, Dd, 0, k, Hh, 0, bk, nullptr, nullptr, 1.f, Dd);
    // 3) vT = (x @ Wv + bv)^T  (A = WvT [Hh,Dd], B = x [MS,Dd], row-bias bv)
    gemm_tf32_nt<<<dim3(Hh / 128, MS / 128, 1), 128, GSMEM_TOTAL>>>(
        wvt, Dd, 0, x, Dd, 0, vT, MS, 0, nullptr, bv, nullptr, 1.f, Dd);
    // 4) scores = q @ k^T / sqrt(H), per batch
    gemm_tf32_nt<<<dim3(Sq / 128, Sq / 128, Bsz), 128, GSMEM_TOTAL>>>(
        q, Hh, (long)Sq * Hh, k, Hh, (long)Sq * Hh, sc, Sq, (long)Sq * Sq,
        nullptr, nullptr, nullptr, inv_sqrt_h, Hh);
    // 5) softmax
    softmax_rows<<<Bsz * Sq, 256>>>(sc, Sq);
    // 6) ctx = P @ V  (B = vT, ldb=MS, per-batch column offset Sq)
    gemm_tf32_nt<<<dim3(Sq / 128, Hh / 128, Bsz), 128, GSMEM_TOTAL>>>(
        sc, Sq, (long)Sq * Sq, vT, MS, Sq, ctx, Hh, (long)Sq * Hh,
        nullptr, nullptr, nullptr, 1.f, Sq);
    // 7) out = ctx @ Wo + bo + x
    gemm_tf32_nt<<<dim3(MS / 128, Dd / 128, 1), 128, GSMEM_TOTAL>>>(
        ctx, Hh, 0, wot, Hh, 0, out, Dd, 0, bo, nullptr, x, 1.f, Hh);
}

// round 4
// speedup vs baseline: 3.7080x; 1.0366x over previous
#include <cuda_runtime.h>
#include <cstdint>
#include <math.h>

// Shapes (fixed)
#define Bsz 8
#define Sq  2048
#define Dd  512
#define Hh  512
#define MS  (Bsz * Sq)   // 16384

// ---------------- scratch (device globals) ----------------
__device__ float g_xr [(long)MS * Dd];      // tf32-rounded x
__device__ float g_q  [(long)MS * Hh];
__device__ float g_k  [(long)MS * Hh];
__device__ float g_vT [(long)MS * Hh];      // [Hh, MS]
__device__ float g_ctx[(long)MS * Hh];
__device__ float g_sc [(long)Bsz * Sq * Sq];
__device__ float g_wqt[Dd * Hh];
__device__ float g_wkt[Dd * Hh];
__device__ float g_wvt[Dd * Hh];
__device__ float g_wot[Dd * Hh];

// ---------------- helpers ----------------
__device__ __forceinline__ uint32_t smem_u32(const void* p) {
    uint32_t a;
    asm("{ .reg .u64 t; cvta.to.shared.u64 t, %1; cvt.u32.u64 %0, t; }" : "=r"(a) : "l"(p));
    return a;
}
__device__ __forceinline__ float tf32r(float x) {
    float r;
    asm("cvt.rna.tf32.f32 %0, %1;" : "=f"(r) : "f"(x));
    return r;
}
#define LDSM4(r, a)                                                              \
    asm volatile("ldmatrix.sync.aligned.m8n8.x4.shared.b16 {%0,%1,%2,%3}, [%4];" \
                 : "=r"((r)[0]), "=r"((r)[1]), "=r"((r)[2]), "=r"((r)[3])        \
                 : "r"(a))
__device__ __forceinline__ void mma_tf32(float* c, const uint32_t* a,
                                         uint32_t b0, uint32_t b1) {
    asm volatile(
        "mma.sync.aligned.m16n8k8.row.col.f32.tf32.tf32.f32 "
        "{%0,%1,%2,%3}, {%4,%5,%6,%7}, {%8,%9}, {%0,%1,%2,%3};"
        : "+f"(c[0]), "+f"(c[1]), "+f"(c[2]), "+f"(c[3])
        : "r"(a[0]), "r"(a[1]), "r"(a[2]), "r"(a[3]), "r"(b0), "r"(b1));
}
#define CP_ASYNC(dst, src) \
    asm volatile("cp.async.cg.shared.global [%0], [%1], 16;" :: "r"(dst), "l"(src))
#define CP_COMMIT() asm volatile("cp.async.commit_group;" ::: "memory")
#define CP_WAIT(n)  asm volatile("cp.async.wait_group %0;" :: "n"(n) : "memory")

// ---------------- tf32 mma.sync NT GEMM ----------------
// C[M,N] = alpha * A[M,K] @ B[N,K]^T (+biasN[col]) (+biasM[row]) (+res)
// All operands must be pre-rounded to tf32. BM=BN=128, BK=32, 256 threads,
// 8 warps in 2(m) x 4(n), warp tile 64x32. 3-stage cp.async pipeline.
#define RS 144                     // padded row stride bytes (36 floats)
#define B_OFF  (128 * RS)          // B tile after A tile within a stage
#define STAGE  (256 * RS)          // 36864 B
#define NSTAGE 3
#define GSMEM_TOTAL (NSTAGE * STAGE)   // 110592 B

__device__ __forceinline__ void stage_load(
    uint32_t sbase, const float* __restrict__ A, long lda,
    const float* __restrict__ B, long ldb, int m0, int n0, int kt, int t)
{
    const int lrow = t >> 3, lch = t & 7;   // lrow 0..31
#pragma unroll
    for (int i = 0; i < 4; i++) {
        const int row = lrow + i * 32;
        CP_ASYNC(sbase + row * RS + lch * 16,
                 A + (long)(m0 + row) * lda + kt + lch * 4);
    }
#pragma unroll
    for (int i = 0; i < 4; i++) {
        const int row = lrow + i * 32;
        CP_ASYNC(sbase + B_OFF + row * RS + lch * 16,
                 B + (long)(n0 + row) * ldb + kt + lch * 4);
    }
}

__global__ __launch_bounds__(256, 2) void gemm_tf32_nt(
    const float* __restrict__ A, long lda, long sA,
    const float* __restrict__ B, long ldb, long sB,
    float* __restrict__ C, long ldc, long sC,
    const float* __restrict__ biasN, const float* __restrict__ biasM,
    const float* __restrict__ res, float alpha, int K, int round_out)
{
    extern __shared__ __align__(128) char smem[];
    const uint32_t sb = smem_u32(smem);
    const int t = threadIdx.x;
    const int m0 = blockIdx.x * 128;
    const int n0 = blockIdx.y * 128;

    A += (long)blockIdx.z * sA;
    B += (long)blockIdx.z * sB;
    C += (long)blockIdx.z * sC;
    const float* resz = res ? res + (long)blockIdx.z * sC : nullptr;

    const int lane = t & 31, w = t >> 5;
    const int wm = w & 1, wn = w >> 1;   // 2 x 4 warp grid

    // ldmatrix per-lane addressing
    const int arow = (lane & 7) + ((lane >> 3) & 1) * 8;
    const int akb  = (lane >> 4) * 16;
    const int brow = ((lane >> 4) * 8) + (lane & 7);
    const int bkb  = ((lane >> 3) & 1) * 16;
    const uint32_t aB = sb + (wm * 64 + arow) * RS + akb;
    const uint32_t bB = sb + B_OFF + (wn * 32 + brow) * RS + bkb;

    float acc[4][4][4];
#pragma unroll
    for (int i = 0; i < 4; i++)
#pragma unroll
        for (int j = 0; j < 4; j++)
#pragma unroll
            for (int r = 0; r < 4; r++) acc[i][j][r] = 0.f;

    const int ktiles = K / 32;
    stage_load(sb, A, lda, B, ldb, m0, n0, 0, t);
    CP_COMMIT();
    if (ktiles > 1) stage_load(sb + STAGE, A, lda, B, ldb, m0, n0, 32, t);
    CP_COMMIT();

    for (int kt = 0; kt < ktiles; kt++) {
        if (kt + 2 < ktiles)
            stage_load(sb + ((kt + 2) % NSTAGE) * STAGE, A, lda, B, ldb,
                       m0, n0, (kt + 2) * 32, t);
        CP_COMMIT();
        CP_WAIT(2);
        __syncthreads();

        const uint32_t so = (kt % NSTAGE) * STAGE;
#pragma unroll
        for (int s = 0; s < 4; s++) {
            uint32_t af[4][4], bf[2][4];
#pragma unroll
            for (int mt = 0; mt < 4; mt++)
                LDSM4(af[mt], aB + so + mt * (16 * RS) + s * 32);
#pragma unroll
            for (int p = 0; p < 2; p++)
                LDSM4(bf[p], bB + so + p * (16 * RS) + s * 32);
#pragma unroll
            for (int mt = 0; mt < 4; mt++)
#pragma unroll
                for (int p = 0; p < 2; p++) {
                    mma_tf32(acc[mt][2 * p + 0], af[mt], bf[p][0], bf[p][1]);
                    mma_tf32(acc[mt][2 * p + 1], af[mt], bf[p][2], bf[p][3]);
                }
        }
        __syncthreads();
    }

    // epilogue
    const int gcol0 = (lane & 3) * 2;
    const int grow  = lane >> 2;
#pragma unroll
    for (int mt = 0; mt < 4; mt++) {
        const long row = m0 + wm * 64 + mt * 16 + grow;
        const float bm0 = biasM ? biasM[row] : 0.f;
        const float bm1 = biasM ? biasM[row + 8] : 0.f;
#pragma unroll
        for (int nt = 0; nt < 4; nt++) {
            const int col = n0 + wn * 32 + nt * 8 + gcol0;
            float2 v0, v1;
            v0.x = acc[mt][nt][0] * alpha + bm0;
            v0.y = acc[mt][nt][1] * alpha + bm0;
            v1.x = acc[mt][nt][2] * alpha + bm1;
            v1.y = acc[mt][nt][3] * alpha + bm1;
            if (biasN) {
                const float2 bb = *(const float2*)(biasN + col);
                v0.x += bb.x; v0.y += bb.y; v1.x += bb.x; v1.y += bb.y;
            }
            if (resz) {
                const float2 r0 = *(const float2*)(resz + row * ldc + col);
                const float2 r1 = *(const float2*)(resz + (row + 8) * ldc + col);
                v0.x += r0.x; v0.y += r0.y; v1.x += r1.x; v1.y += r1.y;
            }
            if (round_out) {
                v0.x = tf32r(v0.x); v0.y = tf32r(v0.y);
                v1.x = tf32r(v1.x); v1.y = tf32r(v1.y);
            }
            *(float2*)(C + row * ldc + col) = v0;
            *(float2*)(C + (row + 8) * ldc + col) = v1;
        }
    }
}

// ---------------- 512x512 transpose (+ tf32 rounding) ----------------
__global__ __launch_bounds__(256) void transpose512(const float* __restrict__ W,
                                                    float* __restrict__ Wt)
{
    __shared__ float tile[32][33];
    const int tx = threadIdx.x, ty = threadIdx.y;  // 32 x 8
    int x = blockIdx.x * 32 + tx;
    int y = blockIdx.y * 32 + ty;
#pragma unroll
    for (int i = 0; i < 4; i++)
        tile[ty + i * 8][tx] = W[(y + i * 8) * 512 + x];
    __syncthreads();
    x = blockIdx.y * 32 + tx;
    y = blockIdx.x * 32 + ty;
#pragma unroll
    for (int i = 0; i < 4; i++)
        Wt[(y + i * 8) * 512 + x] = tf32r(tile[tx][ty + i * 8]);
}

// ---------------- round fp32 -> tf32 (bulk) ----------------
__global__ __launch_bounds__(256) void round_tf32(const float* __restrict__ in,
                                                  float* __restrict__ out, long n4)
{
    const long i = (long)blockIdx.x * blockDim.x + threadIdx.x;
    if (i < n4) {
        float4 v = ((const float4*)in)[i];
        v.x = tf32r(v.x); v.y = tf32r(v.y); v.z = tf32r(v.z); v.w = tf32r(v.w);
        ((float4*)out)[i] = v;
    }
}

// ---------------- softmax (rounds output to tf32) ----------------
__global__ __launch_bounds__(256) void softmax_rows(float* __restrict__ S, int cols)
{
    const long row = blockIdx.x;
    float* p = S + row * (long)cols;
    __shared__ float red[256];
    const int t = threadIdx.x;

    float m = -1e30f;
    for (int c = t; c < cols; c += 256) m = fmaxf(m, p[c]);
    red[t] = m;
    __syncthreads();
    for (int s = 128; s > 0; s >>= 1) {
        if (t < s) red[t] = fmaxf(red[t], red[t + s]);
        __syncthreads();
    }
    m = red[0];
    __syncthreads();

    float sum = 0.f;
    for (int c = t; c < cols; c += 256) {
        float e = __expf(p[c] - m);
        p[c] = e;
        sum += e;
    }
    red[t] = sum;
    __syncthreads();
    for (int s = 128; s > 0; s >>= 1) {
        if (t < s) red[t] += red[t + s];
        __syncthreads();
    }
    const float inv = 1.f / red[0];
    __syncthreads();
    for (int c = t; c < cols; c += 256) p[c] = tf32r(p[c] * inv);
}

// ---------------- launch ----------------
extern "C" void kernel_launch(void* const* d_in, const int* in_sizes, int n_in,
                              void* d_out, int out_size)
{
    const float* x  = (const float*)d_in[0];
    const float* Wq = (const float*)d_in[1];
    const float* bq = (const float*)d_in[2];
    const float* Wk = (const float*)d_in[3];
    const float* bk = (const float*)d_in[4];
    const float* Wv = (const float*)d_in[5];
    const float* bv = (const float*)d_in[6];
    const float* Wo = (const float*)d_in[7];
    const float* bo = (const float*)d_in[8];
    float* out = (float*)d_out;

    float *xr, *q, *k, *vT, *ctx, *sc, *wqt, *wkt, *wvt, *wot;
    cudaGetSymbolAddress((void**)&xr,  g_xr);
    cudaGetSymbolAddress((void**)&q,   g_q);
    cudaGetSymbolAddress((void**)&k,   g_k);
    cudaGetSymbolAddress((void**)&vT,  g_vT);
    cudaGetSymbolAddress((void**)&ctx, g_ctx);
    cudaGetSymbolAddress((void**)&sc,  g_sc);
    cudaGetSymbolAddress((void**)&wqt, g_wqt);
    cudaGetSymbolAddress((void**)&wkt, g_wkt);
    cudaGetSymbolAddress((void**)&wvt, g_wvt);
    cudaGetSymbolAddress((void**)&wot, g_wot);

    static int smem_set = 0;
    if (!smem_set) {
        cudaFuncSetAttribute(gemm_tf32_nt,
                             cudaFuncAttributeMaxDynamicSharedMemorySize, GSMEM_TOTAL);
        smem_set = 1;
    }

    // 0) transpose + round weights; round x
    {
        dim3 g(16, 16), b(32, 8);
        transpose512<<<g, b>>>(Wq, wqt);
        transpose512<<<g, b>>>(Wk, wkt);
        transpose512<<<g, b>>>(Wv, wvt);
        transpose512<<<g, b>>>(Wo, wot);
        const long n4 = (long)MS * Dd / 4;
        round_tf32<<<(n4 + 255) / 256, 256>>>(x, xr, n4);
    }

    const float inv_sqrt_h = 1.f / sqrtf((float)Hh);

    // 1) q = xr @ WqT^T (+bq), rounded
    gemm_tf32_nt<<<dim3(MS / 128, Hh / 128, 1), 256, GSMEM_TOTAL>>>(
        xr, Dd, 0, wqt, Dd, 0, q, Hh, 0, bq, nullptr, nullptr, 1.f, Dd, 1);
    // 2) k, rounded
    gemm_tf32_nt<<<dim3(MS / 128, Hh / 128, 1), 256, GSMEM_TOTAL>>>(
        xr, Dd, 0, wkt, Dd, 0, k, Hh, 0, bk, nullptr, nullptr, 1.f, Dd, 1);
    // 3) vT = (x @ Wv + bv)^T, rounded
    gemm_tf32_nt<<<dim3(Hh / 128, MS / 128, 1), 256, GSMEM_TOTAL>>>(
        wvt, Dd, 0, xr, Dd, 0, vT, MS, 0, nullptr, bv, nullptr, 1.f, Dd, 1);
    // 4) scores = q @ k^T / sqrt(H), per batch, rounded
    gemm_tf32_nt<<<dim3(Sq / 128, Sq / 128, Bsz), 256, GSMEM_TOTAL>>>(
        q, Hh, (long)Sq * Hh, k, Hh, (long)Sq * Hh, sc, Sq, (long)Sq * Sq,
        nullptr, nullptr, nullptr, inv_sqrt_h, Hh, 1);
    // 5) softmax (rounds output)
    softmax_rows<<<Bsz * Sq, 256>>>(sc, Sq);
    // 6) ctx = P @ V, rounded
    gemm_tf32_nt<<<dim3(Sq / 128, Hh / 128, Bsz), 256, GSMEM_TOTAL>>>(
        sc, Sq, (long)Sq * Sq, vT, MS, Sq, ctx, Hh, (long)Sq * Hh,
        nullptr, nullptr, nullptr, 1.f, Sq, 1);
    // 7) out = ctx @ Wo + bo + x  (NOT rounded)
    gemm_tf32_nt<<<dim3(MS / 128, Dd / 128, 1), 256, GSMEM_TOTAL>>>(
        ctx, Hh, 0, wot, Hh, 0, out, Dd, 0, bo, nullptr, x, 1.f, Hh, 0);
}

// round 5
// speedup vs baseline: 5.8210x; 1.5699x over previous
#include <cuda_runtime.h>
#include <cuda_bf16.h>
#include <cstdint>
#include <math.h>

// Shapes (fixed)
#define Bsz 8
#define Sq  2048
#define Dd  512
#define Hh  512
#define MS  (Bsz * Sq)   // 16384

// ---------------- scratch (device globals) ----------------
__device__ __nv_bfloat16 g_xb [(long)MS * Dd];
__device__ __nv_bfloat16 g_qb [(long)MS * Hh];
__device__ __nv_bfloat16 g_kb [(long)MS * Hh];
__device__ __nv_bfloat16 g_vTb[(long)MS * Hh];      // [Hh, MS]
__device__ __nv_bfloat16 g_ctxb[(long)MS * Hh];
__device__ float         g_sc [(long)Bsz * Sq * Sq];  // fp32 scores
__device__ __nv_bfloat16 g_p  [(long)Bsz * Sq * Sq];  // bf16 probs
__device__ __nv_bfloat16 g_wqt[Dd * Hh];
__device__ __nv_bfloat16 g_wkt[Dd * Hh];
__device__ __nv_bfloat16 g_wvt[Dd * Hh];
__device__ __nv_bfloat16 g_wot[Dd * Hh];

// ---------------- helpers ----------------
__device__ __forceinline__ uint32_t smem_u32(const void* p) {
    uint32_t a;
    asm("{ .reg .u64 t; cvta.to.shared.u64 t, %1; cvt.u32.u64 %0, t; }" : "=r"(a) : "l"(p));
    return a;
}
#define LDSM4(r, a)                                                              \
    asm volatile("ldmatrix.sync.aligned.m8n8.x4.shared.b16 {%0,%1,%2,%3}, [%4];" \
                 : "=r"((r)[0]), "=r"((r)[1]), "=r"((r)[2]), "=r"((r)[3])        \
                 : "r"(a))
__device__ __forceinline__ void mma_bf16(float* c, const uint32_t* a,
                                         uint32_t b0, uint32_t b1) {
    asm volatile(
        "mma.sync.aligned.m16n8k16.row.col.f32.bf16.bf16.f32 "
        "{%0,%1,%2,%3}, {%4,%5,%6,%7}, {%8,%9}, {%0,%1,%2,%3};"
        : "+f"(c[0]), "+f"(c[1]), "+f"(c[2]), "+f"(c[3])
        : "r"(a[0]), "r"(a[1]), "r"(a[2]), "r"(a[3]), "r"(b0), "r"(b1));
}
#define CP_ASYNC(dst, src) \
    asm volatile("cp.async.cg.shared.global [%0], [%1], 16;" :: "r"(dst), "l"(src))
#define CP_COMMIT() asm volatile("cp.async.commit_group;" ::: "memory")
#define CP_WAIT(n)  asm volatile("cp.async.wait_group %0;" :: "n"(n) : "memory")

// ---------------- bf16 mma.sync NT GEMM ----------------
// C[M,N] = alpha * A[M,K] @ B[N,K]^T (+biasN[col]) (+biasM[row]) (+res)
// A,B bf16 K-major. BM=BN=128, BK=64, 256 threads, 8 warps 2(m)x4(n),
// warp tile 64x32. 3-stage cp.async pipeline. K % 64 == 0.
#define RS 144                     // padded row stride bytes (64 bf16 = 128B + 16 pad)
#define B_OFF  (128 * RS)
#define STAGE  (256 * RS)          // 36864 B
#define NSTAGE 3
#define GSMEM_TOTAL (NSTAGE * STAGE)   // 110592 B

__device__ __forceinline__ void stage_load(
    uint32_t sbase, const __nv_bfloat16* __restrict__ A, long lda,
    const __nv_bfloat16* __restrict__ B, long ldb, int m0, int n0, int kt, int t)
{
    const int lrow = t >> 3, lch = t & 7;   // lrow 0..31, 8 x 16B chunks per row
#pragma unroll
    for (int i = 0; i < 4; i++) {
        const int row = lrow + i * 32;
        CP_ASYNC(sbase + row * RS + lch * 16,
                 A + (long)(m0 + row) * lda + kt + lch * 8);
    }
#pragma unroll
    for (int i = 0; i < 4; i++) {
        const int row = lrow + i * 32;
        CP_ASYNC(sbase + B_OFF + row * RS + lch * 16,
                 B + (long)(n0 + row) * ldb + kt + lch * 8);
    }
}

__global__ __launch_bounds__(256, 2) void gemm_bf16_nt(
    const __nv_bfloat16* __restrict__ A, long lda, long sA,
    const __nv_bfloat16* __restrict__ B, long ldb, long sB,
    void* __restrict__ Cv, long ldc, long sC,
    const float* __restrict__ biasN, const float* __restrict__ biasM,
    const float* __restrict__ res, float alpha, int K, int c_bf16)
{
    extern __shared__ __align__(128) char smem[];
    const uint32_t sb = smem_u32(smem);
    const int t = threadIdx.x;
    const int m0 = blockIdx.x * 128;
    const int n0 = blockIdx.y * 128;

    A += (long)blockIdx.z * sA;
    B += (long)blockIdx.z * sB;
    const float* resz = res ? res + (long)blockIdx.z * sC : nullptr;

    const int lane = t & 31, w = t >> 5;
    const int wm = w & 1, wn = w >> 1;   // 2 x 4 warp grid

    // ldmatrix addressing: (lane&15) = row within 16-row frag, (lane>>4) = 16B k-half
    const uint32_t aB = sb + (wm * 64 + (lane & 15)) * RS + (lane >> 4) * 16;
    const uint32_t bB = sb + B_OFF + (wn * 32 + (lane & 15)) * RS + (lane >> 4) * 16;

    float acc[4][4][4];
#pragma unroll
    for (int i = 0; i < 4; i++)
#pragma unroll
        for (int j = 0; j < 4; j++)
#pragma unroll
            for (int r = 0; r < 4; r++) acc[i][j][r] = 0.f;

    const int ktiles = K / 64;
    stage_load(sb, A, lda, B, ldb, m0, n0, 0, t);
    CP_COMMIT();
    if (ktiles > 1) stage_load(sb + STAGE, A, lda, B, ldb, m0, n0, 64, t);
    CP_COMMIT();

    for (int kt = 0; kt < ktiles; kt++) {
        if (kt + 2 < ktiles)
            stage_load(sb + ((kt + 2) % NSTAGE) * STAGE, A, lda, B, ldb,
                       m0, n0, (kt + 2) * 64, t);
        CP_COMMIT();
        CP_WAIT(2);
        __syncthreads();

        const uint32_t so = (kt % NSTAGE) * STAGE;
#pragma unroll
        for (int s = 0; s < 4; s++) {      // 4 k-steps of 16
            uint32_t af[4][4], bf[2][4];
#pragma unroll
            for (int mt = 0; mt < 4; mt++)
                LDSM4(af[mt], aB + so + mt * (16 * RS) + s * 32);
#pragma unroll
            for (int p = 0; p < 2; p++)
                LDSM4(bf[p], bB + so + p * (16 * RS) + s * 32);
#pragma unroll
            for (int mt = 0; mt < 4; mt++)
#pragma unroll
                for (int p = 0; p < 2; p++) {
                    // reg map: r0=n0-7/k0-7, r1=n8-15/k0-7, r2=n0-7/k8-15, r3=n8-15/k8-15
                    mma_bf16(acc[mt][2 * p + 0], af[mt], bf[p][0], bf[p][2]);
                    mma_bf16(acc[mt][2 * p + 1], af[mt], bf[p][1], bf[p][3]);
                }
        }
        __syncthreads();
    }

    // epilogue
    const int gcol0 = (lane & 3) * 2;
    const int grow  = lane >> 2;
#pragma unroll
    for (int mt = 0; mt < 4; mt++) {
        const long row = m0 + wm * 64 + mt * 16 + grow;
        const float bm0 = biasM ? biasM[row] : 0.f;
        const float bm1 = biasM ? biasM[row + 8] : 0.f;
#pragma unroll
        for (int nt = 0; nt < 4; nt++) {
            const int col = n0 + wn * 32 + nt * 8 + gcol0;
            float2 v0, v1;
            v0.x = acc[mt][nt][0] * alpha + bm0;
            v0.y = acc[mt][nt][1] * alpha + bm0;
            v1.x = acc[mt][nt][2] * alpha + bm1;
            v1.y = acc[mt][nt][3] * alpha + bm1;
            if (biasN) {
                const float2 bb = *(const float2*)(biasN + col);
                v0.x += bb.x; v0.y += bb.y; v1.x += bb.x; v1.y += bb.y;
            }
            if (resz) {
                const float2 r0 = *(const float2*)(resz + row * ldc + col);
                const float2 r1 = *(const float2*)(resz + (row + 8) * ldc + col);
                v0.x += r0.x; v0.y += r0.y; v1.x += r1.x; v1.y += r1.y;
            }
            if (c_bf16) {
                __nv_bfloat16* C = (__nv_bfloat16*)Cv + (long)blockIdx.z * sC;
                *(__nv_bfloat162*)(C + row * ldc + col) = __float22bfloat162_rn(v0);
                *(__nv_bfloat162*)(C + (row + 8) * ldc + col) = __float22bfloat162_rn(v1);
            } else {
                float* C = (float*)Cv + (long)blockIdx.z * sC;
                *(float2*)(C + row * ldc + col) = v0;
                *(float2*)(C + (row + 8) * ldc + col) = v1;
            }
        }
    }
}

// ---------------- 512x512 transpose -> bf16 ----------------
__global__ __launch_bounds__(256) void transpose512(const float* __restrict__ W,
                                                    __nv_bfloat16* __restrict__ Wt)
{
    __shared__ float tile[32][33];
    const int tx = threadIdx.x, ty = threadIdx.y;  // 32 x 8
    int x = blockIdx.x * 32 + tx;
    int y = blockIdx.y * 32 + ty;
#pragma unroll
    for (int i = 0; i < 4; i++)
        tile[ty + i * 8][tx] = W[(y + i * 8) * 512 + x];
    __syncthreads();
    x = blockIdx.y * 32 + tx;
    y = blockIdx.x * 32 + ty;
#pragma unroll
    for (int i = 0; i < 4; i++)
        Wt[(y + i * 8) * 512 + x] = __float2bfloat16_rn(tile[tx][ty + i * 8]);
}

// ---------------- fp32 -> bf16 bulk convert ----------------
__global__ __launch_bounds__(256) void cvt_bf16(const float* __restrict__ in,
                                                __nv_bfloat16* __restrict__ out, long n4)
{
    const long i = (long)blockIdx.x * blockDim.x + threadIdx.x;
    if (i < n4) {
        float4 v = ((const float4*)in)[i];
        __nv_bfloat162 a = __float22bfloat162_rn(make_float2(v.x, v.y));
        __nv_bfloat162 b = __float22bfloat162_rn(make_float2(v.z, v.w));
        *(__nv_bfloat162*)(out + i * 4)     = a;
        *(__nv_bfloat162*)(out + i * 4 + 2) = b;
    }
}

// ---------------- softmax: fp32 in, bf16 out, one pass ----------------
// 2048 cols, 256 threads, 8 vals/thread held in registers.
__global__ __launch_bounds__(256) void softmax_rows(const float* __restrict__ S,
                                                    __nv_bfloat16* __restrict__ P)
{
    const long row = blockIdx.x;
    const float* p = S + row * (long)Sq;
    __nv_bfloat16* o = P + row * (long)Sq;
    __shared__ float red[256];
    const int t = threadIdx.x;

    float v[8];
    float4 x0 = *(const float4*)(p + t * 8);
    float4 x1 = *(const float4*)(p + t * 8 + 4);
    v[0] = x0.x; v[1] = x0.y; v[2] = x0.z; v[3] = x0.w;
    v[4] = x1.x; v[5] = x1.y; v[6] = x1.z; v[7] = x1.w;

    float m = v[0];
#pragma unroll
    for (int i = 1; i < 8; i++) m = fmaxf(m, v[i]);
    red[t] = m;
    __syncthreads();
    for (int s = 128; s > 0; s >>= 1) {
        if (t < s) red[t] = fmaxf(red[t], red[t + s]);
        __syncthreads();
    }
    m = red[0];
    __syncthreads();

    float sum = 0.f;
#pragma unroll
    for (int i = 0; i < 8; i++) { v[i] = __expf(v[i] - m); sum += v[i]; }
    red[t] = sum;
    __syncthreads();
    for (int s = 128; s > 0; s >>= 1) {
        if (t < s) red[t] += red[t + s];
        __syncthreads();
    }
    const float inv = 1.f / red[0];

    __nv_bfloat162 ob[4];
#pragma unroll
    for (int i = 0; i < 4; i++)
        ob[i] = __float22bfloat162_rn(make_float2(v[2 * i] * inv, v[2 * i + 1] * inv));
    *(__nv_bfloat162*)(o + t * 8)     = ob[0];
    *(__nv_bfloat162*)(o + t * 8 + 2) = ob[1];
    *(__nv_bfloat162*)(o + t * 8 + 4) = ob[2];
    *(__nv_bfloat162*)(o + t * 8 + 6) = ob[3];
}

// ---------------- launch ----------------
extern "C" void kernel_launch(void* const* d_in, const int* in_sizes, int n_in,
                              void* d_out, int out_size)
{
    const float* x  = (const float*)d_in[0];
    const float* Wq = (const float*)d_in[1];
    const float* bq = (const float*)d_in[2];
    const float* Wk = (const float*)d_in[3];
    const float* bk = (const float*)d_in[4];
    const float* Wv = (const float*)d_in[5];
    const float* bv = (const float*)d_in[6];
    const float* Wo = (const float*)d_in[7];
    const float* bo = (const float*)d_in[8];
    float* out = (float*)d_out;

    __nv_bfloat16 *xb, *qb, *kb, *vTb, *ctxb, *pb, *wqt, *wkt, *wvt, *wot;
    float* sc;
    cudaGetSymbolAddress((void**)&xb,   g_xb);
    cudaGetSymbolAddress((void**)&qb,   g_qb);
    cudaGetSymbolAddress((void**)&kb,   g_kb);
    cudaGetSymbolAddress((void**)&vTb,  g_vTb);
    cudaGetSymbolAddress((void**)&ctxb, g_ctxb);
    cudaGetSymbolAddress((void**)&pb,   g_p);
    cudaGetSymbolAddress((void**)&sc,   g_sc);
    cudaGetSymbolAddress((void**)&wqt,  g_wqt);
    cudaGetSymbolAddress((void**)&wkt,  g_wkt);
    cudaGetSymbolAddress((void**)&wvt,  g_wvt);
    cudaGetSymbolAddress((void**)&wot,  g_wot);

    static int smem_set = 0;
    if (!smem_set) {
        cudaFuncSetAttribute(gemm_bf16_nt,
                             cudaFuncAttributeMaxDynamicSharedMemorySize, GSMEM_TOTAL);
        smem_set = 1;
    }

    // 0) transpose + convert weights; convert x
    {
        dim3 g(16, 16), b(32, 8);
        transpose512<<<g, b>>>(Wq, wqt);
        transpose512<<<g, b>>>(Wk, wkt);
        transpose512<<<g, b>>>(Wv, wvt);
        transpose512<<<g, b>>>(Wo, wot);
        const long n4 = (long)MS * Dd / 4;
        cvt_bf16<<<(n4 + 255) / 256, 256>>>(x, xb, n4);
    }

    const float inv_sqrt_h = 1.f / sqrtf((float)Hh);

    // 1) q = x @ Wq (+bq) -> bf16
    gemm_bf16_nt<<<dim3(MS / 128, Hh / 128, 1), 256, GSMEM_TOTAL>>>(
        xb, Dd, 0, wqt, Dd, 0, qb, Hh, 0, bq, nullptr, nullptr, 1.f, Dd, 1);
    // 2) k -> bf16
    gemm_bf16_nt<<<dim3(MS / 128, Hh / 128, 1), 256, GSMEM_TOTAL>>>(
        xb, Dd, 0, wkt, Dd, 0, kb, Hh, 0, bk, nullptr, nullptr, 1.f, Dd, 1);
    // 3) vT = (x @ Wv + bv)^T -> bf16  (A = WvT [Hh,Dd], B = x [MS,Dd], row-bias bv)
    gemm_bf16_nt<<<dim3(Hh / 128, MS / 128, 1), 256, GSMEM_TOTAL>>>(
        wvt, Dd, 0, xb, Dd, 0, vTb, MS, 0, nullptr, bv, nullptr, 1.f, Dd, 1);
    // 4) scores = q @ k^T / sqrt(H) -> fp32, per batch
    gemm_bf16_nt<<<dim3(Sq / 128, Sq / 128, Bsz), 256, GSMEM_TOTAL>>>(
        qb, Hh, (long)Sq * Hh, kb, Hh, (long)Sq * Hh, sc, Sq, (long)Sq * Sq,
        nullptr, nullptr, nullptr, inv_sqrt_h, Hh, 0);
    // 5) softmax fp32 -> bf16
    softmax_rows<<<Bsz * Sq, 256>>>(sc, pb);
    // 6) ctx = P @ V -> bf16  (B = vTb, ldb=MS, per-batch column offset Sq)
    gemm_bf16_nt<<<dim3(Sq / 128, Hh / 128, Bsz), 256, GSMEM_TOTAL>>>(
        pb, Sq, (long)Sq * Sq, vTb, MS, Sq, ctxb, Hh, (long)Sq * Hh,
        nullptr, nullptr, nullptr, 1.f, Sq, 1);
    // 7) out = ctx @ Wo + bo + x -> fp32
    gemm_bf16_nt<<<dim3(MS / 128, Dd / 128, 1), 256, GSMEM_TOTAL>>>(
        ctxb, Hh, 0, wot, Hh, 0, out, Dd, 0, bo, nullptr, x, 1.f, Hh, 0);
}